// round 1
// baseline (speedup 1.0000x reference)
#include <cuda_runtime.h>
#include <math.h>

// Problem dims (fixed by the dataset)
constexpr int M_DIM = 4 * 2048;      // 8192 rows of x
constexpr int N_DIM = 4096;          // OUT_FEATURES
constexpr int K_DIM = 4096;          // IN_FEATURES
constexpr int GROUPS = K_DIM / 32;   // 128 int32 groups per output row
constexpr int PLANE_STRIDE = N_DIM * GROUPS;  // elements between bitplanes

// Scratch: effective dequantized weight Weff[N][K], fp32 (64 MB).
// __device__ global array == allowed scratch (no runtime allocation).
__device__ float g_weff[(size_t)N_DIM * K_DIM];

// ---------------------------------------------------------------------------
// Kernel 1: dequant + blend into Weff.
// One thread per 32-weight group. code4 = planes 0..3 (plane0 = MSB),
// code5 = planes 0..4 (plane0 = MSB); bit i%32 of the int32, LSB-first.
// Weff = r*lut4[c4] + (1-r)*lut5[c5].
// ---------------------------------------------------------------------------
__global__ __launch_bounds__(256) void dequant_kernel(
    const int* __restrict__ qweight,
    const float* __restrict__ lut4,
    const float* __restrict__ lut5,
    const float* __restrict__ zp)
{
    int idx = blockIdx.x * blockDim.x + threadIdx.x;   // 0 .. N*GROUPS-1
    int o = idx >> 7;          // output row (GROUPS = 128)
    int g = idx & (GROUPS - 1);

    int base = o * GROUPS + g;
    unsigned q0 = (unsigned)qweight[base];
    unsigned q1 = (unsigned)qweight[base + PLANE_STRIDE];
    unsigned q2 = (unsigned)qweight[base + 2 * PLANE_STRIDE];
    unsigned q3 = (unsigned)qweight[base + 3 * PLANE_STRIDE];
    unsigned q4 = (unsigned)qweight[base + 4 * PLANE_STRIDE];

    // r = 1 - (p - BL), p = sigmoid(z)*3 + 3, BL = 4  =>  r = 2 - 3*sigmoid(z)
    float z = zp[0];
    float sig = 1.0f / (1.0f + expf(-z));
    float r = 2.0f - 3.0f * sig;
    float s = 1.0f - r;

    const float* l4 = lut4 + o * 16;
    const float* l5 = lut5 + o * 32;
    float* dst = g_weff + (size_t)o * K_DIM + g * 32;

    float vals[32];
#pragma unroll
    for (int b = 0; b < 32; b++) {
        unsigned c4 = (((q0 >> b) & 1u) << 3) | (((q1 >> b) & 1u) << 2)
                    | (((q2 >> b) & 1u) << 1) |  ((q3 >> b) & 1u);
        unsigned c5 = (c4 << 1) | ((q4 >> b) & 1u);
        vals[b] = r * l4[c4] + s * l5[c5];
    }
#pragma unroll
    for (int b = 0; b < 32; b += 4) {
        float4 v = make_float4(vals[b], vals[b + 1], vals[b + 2], vals[b + 3]);
        *reinterpret_cast<float4*>(dst + b) = v;
    }
}

// ---------------------------------------------------------------------------
// Kernel 2: fp32 GEMM  Y[M][N] = X[M][K] * Weff[N][K]^T + bias[N]
// 128x128 block tile, BK=16, 256 threads, 8x8 per-thread microtile.
// Both A and B are K-major, loaded as float4 and stored transposed to smem.
// ---------------------------------------------------------------------------
constexpr int BM = 128, BN = 128, BK = 16, TM = 8, TN = 8;

__global__ __launch_bounds__(256) void gemm_kernel(
    const float* __restrict__ A,     // X   [M][K]
    const float* __restrict__ bias,  // [N]
    float* __restrict__ C)           // Y   [M][N]
{
    __shared__ float As[BK][BM];
    __shared__ float Bs[BK][BN];

    const float* B = g_weff;         // Weff [N][K]

    int tid = threadIdx.x;
    int mBase = blockIdx.y * BM;
    int nBase = blockIdx.x * BN;

    int ty = tid >> 4;               // 0..15 (M direction)
    int tx = tid & 15;               // 0..15 (N direction)

    const float* Aptr = A + (size_t)mBase * K_DIM;
    const float* Bptr = B + (size_t)nBase * K_DIM;

    float acc[TM][TN];
#pragma unroll
    for (int i = 0; i < TM; i++)
#pragma unroll
        for (int j = 0; j < TN; j++) acc[i][j] = 0.0f;

    for (int k0 = 0; k0 < K_DIM; k0 += BK) {
        // Cooperative load: 128x16 tile = 512 float4 per matrix, 2 per thread.
#pragma unroll
        for (int it = 0; it < 2; it++) {
            int f = tid + it * 256;          // float4 index
            int row = f >> 2;                // 0..127
            int cv = (f & 3) << 2;           // 0,4,8,12

            float4 av = *reinterpret_cast<const float4*>(
                Aptr + (size_t)row * K_DIM + k0 + cv);
            As[cv + 0][row] = av.x; As[cv + 1][row] = av.y;
            As[cv + 2][row] = av.z; As[cv + 3][row] = av.w;

            float4 bv = *reinterpret_cast<const float4*>(
                Bptr + (size_t)row * K_DIM + k0 + cv);
            Bs[cv + 0][row] = bv.x; Bs[cv + 1][row] = bv.y;
            Bs[cv + 2][row] = bv.z; Bs[cv + 3][row] = bv.w;
        }
        __syncthreads();

#pragma unroll
        for (int k = 0; k < BK; k++) {
            float a[TM], b[TN];
            *reinterpret_cast<float4*>(&a[0]) =
                *reinterpret_cast<const float4*>(&As[k][ty * TM]);
            *reinterpret_cast<float4*>(&a[4]) =
                *reinterpret_cast<const float4*>(&As[k][ty * TM + 4]);
            *reinterpret_cast<float4*>(&b[0]) =
                *reinterpret_cast<const float4*>(&Bs[k][tx * TN]);
            *reinterpret_cast<float4*>(&b[4]) =
                *reinterpret_cast<const float4*>(&Bs[k][tx * TN + 4]);
#pragma unroll
            for (int i = 0; i < TM; i++)
#pragma unroll
                for (int j = 0; j < TN; j++)
                    acc[i][j] = fmaf(a[i], b[j], acc[i][j]);
        }
        __syncthreads();
    }

    // Epilogue: add bias, vectorized store.
#pragma unroll
    for (int i = 0; i < TM; i++) {
        int m = mBase + ty * TM + i;
        float* crow = C + (size_t)m * N_DIM;
#pragma unroll
        for (int j = 0; j < TN; j += 4) {
            int n = nBase + tx * TN + j;
            float4 v;
            v.x = acc[i][j + 0] + bias[n + 0];
            v.y = acc[i][j + 1] + bias[n + 1];
            v.z = acc[i][j + 2] + bias[n + 2];
            v.w = acc[i][j + 3] + bias[n + 3];
            *reinterpret_cast<float4*>(crow + n) = v;
        }
    }
}

// ---------------------------------------------------------------------------
// Launch: inputs in metadata order: x, z, lut4, lut5, bias, qweight
// ---------------------------------------------------------------------------
extern "C" void kernel_launch(void* const* d_in, const int* in_sizes, int n_in,
                              void* d_out, int out_size)
{
    const float* x    = (const float*)d_in[0];
    const float* z    = (const float*)d_in[1];
    const float* lut4 = (const float*)d_in[2];
    const float* lut5 = (const float*)d_in[3];
    const float* bias = (const float*)d_in[4];
    const int* qweight = (const int*)d_in[5];
    float* out = (float*)d_out;

    (void)in_sizes; (void)n_in; (void)out_size;

    // Kernel 1: dequant + blend (N*GROUPS = 524288 threads)
    dequant_kernel<<<(N_DIM * GROUPS) / 256, 256>>>(qweight, lut4, lut5, z);

    // Kernel 2: GEMM + bias
    dim3 grid(N_DIM / BN, M_DIM / BM);   // (32, 64)
    gemm_kernel<<<grid, 256>>>(x, bias, out);
}

// round 6
// speedup vs baseline: 3.7229x; 3.7229x over previous
#include <cuda_runtime.h>
#include <cstdint>
#include <math.h>

// ---------------------------------------------------------------------------
// Problem dims
// ---------------------------------------------------------------------------
constexpr int M_DIM = 8192;
constexpr int N_DIM = 4096;
constexpr int K_DIM = 4096;
constexpr int GROUPS = K_DIM / 32;
constexpr int PLANE_STRIDE = N_DIM * GROUPS;

// Scratch (static device arrays = allowed). tf32-rounded fp32 operands.
__device__ float g_xt[(size_t)M_DIM * K_DIM];   // 134 MB
__device__ float g_wt[(size_t)N_DIM * K_DIM];   // 67 MB

// ---------------------------------------------------------------------------
// Helpers (base ISA only — compute_103-safe: no tcgen05 / no 'a' features)
// ---------------------------------------------------------------------------
__device__ __forceinline__ uint32_t smem_to_u32(const void* p) {
    uint32_t a;
    asm("{ .reg .u64 t; cvta.to.shared.u64 t, %1; cvt.u32.u64 %0, t; }"
        : "=r"(a) : "l"(p));
    return a;
}

__device__ __forceinline__ float to_tf32(float x) {
    float r;
    asm("cvt.rna.tf32.f32 %0, %1;" : "=f"(r) : "f"(x));
    return r;
}

#define CP_ASYNC16(dst, src) \
    asm volatile("cp.async.cg.shared.global [%0], [%1], 16;" :: "r"(dst), "l"(src) : "memory")
#define CP_COMMIT() asm volatile("cp.async.commit_group;" ::: "memory")
#define CP_WAIT1()  asm volatile("cp.async.wait_group 1;" ::: "memory")

__device__ __forceinline__ void mma_tf32(float* d, const float* a, const float* b) {
    asm volatile(
        "mma.sync.aligned.m16n8k8.row.col.f32.tf32.tf32.f32 "
        "{%0,%1,%2,%3}, {%4,%5,%6,%7}, {%8,%9}, {%0,%1,%2,%3};"
        : "+f"(d[0]), "+f"(d[1]), "+f"(d[2]), "+f"(d[3])
        : "r"(__float_as_uint(a[0])), "r"(__float_as_uint(a[1])),
          "r"(__float_as_uint(a[2])), "r"(__float_as_uint(a[3])),
          "r"(__float_as_uint(b[0])), "r"(__float_as_uint(b[1])));
}

// ---------------------------------------------------------------------------
// Kernel 1: dequant + blend -> W (tf32-rounded fp32)
// ---------------------------------------------------------------------------
__global__ __launch_bounds__(256) void dequant_w(
    const int* __restrict__ qw, const float* __restrict__ lut4,
    const float* __restrict__ lut5, const float* __restrict__ zp)
{
    int idx = blockIdx.x * 256 + threadIdx.x;
    int o = idx >> 7;
    int g = idx & (GROUPS - 1);
    int base = o * GROUPS + g;

    unsigned q0 = (unsigned)qw[base];
    unsigned q1 = (unsigned)qw[base + PLANE_STRIDE];
    unsigned q2 = (unsigned)qw[base + 2 * PLANE_STRIDE];
    unsigned q3 = (unsigned)qw[base + 3 * PLANE_STRIDE];
    unsigned q4 = (unsigned)qw[base + 4 * PLANE_STRIDE];

    float z = zp[0];
    float r = 2.0f - 3.0f / (1.0f + expf(-z));   // 2 - 3*sigmoid(z)
    float s = 1.0f - r;

    const float* l4 = lut4 + o * 16;
    const float* l5 = lut5 + o * 32;

    float vals[32];
#pragma unroll
    for (int b = 0; b < 32; b++) {
        unsigned c4 = (((q0 >> b) & 1u) << 3) | (((q1 >> b) & 1u) << 2)
                    | (((q2 >> b) & 1u) << 1) |  ((q3 >> b) & 1u);
        unsigned c5 = (c4 << 1) | ((q4 >> b) & 1u);
        vals[b] = to_tf32(r * l4[c4] + s * l5[c5]);
    }
    float* dst = g_wt + (size_t)o * K_DIM + g * 32;
#pragma unroll
    for (int b = 0; b < 32; b += 4)
        *reinterpret_cast<float4*>(dst + b) =
            make_float4(vals[b], vals[b + 1], vals[b + 2], vals[b + 3]);
}

// ---------------------------------------------------------------------------
// Kernel 2: x -> tf32-rounded fp32
// ---------------------------------------------------------------------------
__global__ __launch_bounds__(256) void convert_x(const float* __restrict__ x)
{
    size_t i = ((size_t)blockIdx.x * 256 + threadIdx.x) * 8;
    float4 a = *reinterpret_cast<const float4*>(x + i);
    float4 b = *reinterpret_cast<const float4*>(x + i + 4);
    a.x = to_tf32(a.x); a.y = to_tf32(a.y); a.z = to_tf32(a.z); a.w = to_tf32(a.w);
    b.x = to_tf32(b.x); b.y = to_tf32(b.y); b.z = to_tf32(b.z); b.w = to_tf32(b.w);
    *reinterpret_cast<float4*>(g_xt + i) = a;
    *reinterpret_cast<float4*>(g_xt + i + 4) = b;
}

// ---------------------------------------------------------------------------
// Kernel 3: tf32 mma.sync GEMM.  out[M][N] = xt @ wt^T + bias
// CTA 256x128, BK=32, 3-stage cp.async pipeline, 8 warps (4x2), warp 64x64.
// Smem [row][k] with PADK=36 floats -> conflict-free fragment gathers.
// ---------------------------------------------------------------------------
constexpr int BM = 256, BN = 128, BK = 32;
constexpr int STAGES = 3;
constexpr int PADK = 36;
constexpr int ROWS = BM + BN;                 // 384
constexpr int STAGE_FLOATS = ROWS * PADK;     // 13824
constexpr int NCHUNK = K_DIM / BK;            // 128
constexpr int SMEM_BYTES = STAGES * STAGE_FLOATS * 4;  // 165888

__global__ __launch_bounds__(256, 1) void gemm_tf32(
    const float* __restrict__ bias, float* __restrict__ out)
{
    extern __shared__ float sm[];
    const int tid = threadIdx.x;
    const int lane = tid & 31, wid = tid >> 5;
    const int wm = wid >> 1, wn = wid & 1;       // warp grid 4x2
    const int grp = lane >> 2, qid = lane & 3;
    const int mBase = blockIdx.y * BM;
    const int nBase = blockIdx.x * BN;

    const float* Ag = g_xt + (size_t)mBase * K_DIM;
    const float* Bg = g_wt + (size_t)nBase * K_DIM;
    const uint32_t smAddr = smem_to_u32(sm);

    float acc[4][8][4];
#pragma unroll
    for (int i = 0; i < 4; i++)
#pragma unroll
        for (int j = 0; j < 8; j++)
#pragma unroll
            for (int t = 0; t < 4; t++) acc[i][j][t] = 0.0f;

    // -- async load of one BK-chunk into stage (c % STAGES) --
    auto load_chunk = [&](int c) {
        uint32_t stAddr = smAddr + (uint32_t)((c % STAGES) * STAGE_FLOATS * 4);
#pragma unroll
        for (int it = 0; it < 12; it++) {           // 3072 16B ops / 256 thr
            int f = tid + it * 256;
            int row = f >> 3;
            int seg = f & 7;                        // 16B segment in the 128B row
            const float* src = (row < BM
                ? Ag + (size_t)row * K_DIM
                : Bg + (size_t)(row - BM) * K_DIM) + c * BK + seg * 4;
            uint32_t dst = stAddr + (uint32_t)((row * PADK + seg * 4) * 4);
            CP_ASYNC16(dst, src);
        }
    };

    load_chunk(0); CP_COMMIT();
    load_chunk(1); CP_COMMIT();

    for (int c = 0; c < NCHUNK; c++) {
        CP_WAIT1();            // group c complete
        __syncthreads();       // visible to all; all warps past compute(c-1)

        if (c + 2 < NCHUNK) load_chunk(c + 2);
        CP_COMMIT();           // keep group accounting aligned

        const float* st = sm + (c % STAGES) * STAGE_FLOATS;
#pragma unroll
        for (int ks = 0; ks < 4; ks++) {
            const int k0 = ks * 8;
            float a[4][4], b[8][2];
#pragma unroll
            for (int mt = 0; mt < 4; mt++) {
                int m = wm * 64 + mt * 16 + grp;
                a[mt][0] = st[m * PADK + k0 + qid];
                a[mt][1] = st[(m + 8) * PADK + k0 + qid];
                a[mt][2] = st[m * PADK + k0 + qid + 4];
                a[mt][3] = st[(m + 8) * PADK + k0 + qid + 4];
            }
#pragma unroll
            for (int nt = 0; nt < 8; nt++) {
                int n = wn * 64 + nt * 8 + grp;
                b[nt][0] = st[(BM + n) * PADK + k0 + qid];
                b[nt][1] = st[(BM + n) * PADK + k0 + qid + 4];
            }
#pragma unroll
            for (int mt = 0; mt < 4; mt++)
#pragma unroll
                for (int nt = 0; nt < 8; nt++)
                    mma_tf32(acc[mt][nt], a[mt], b[nt]);
        }
    }

    // -- epilogue: bias + float2 stores --
#pragma unroll
    for (int mt = 0; mt < 4; mt++) {
        int m0 = mBase + wm * 64 + mt * 16 + grp;
#pragma unroll
        for (int nt = 0; nt < 8; nt++) {
            int n0 = nBase + wn * 64 + nt * 8 + 2 * qid;
            float2 bv = *reinterpret_cast<const float2*>(bias + n0);
            float2 v0 = make_float2(acc[mt][nt][0] + bv.x, acc[mt][nt][1] + bv.y);
            float2 v1 = make_float2(acc[mt][nt][2] + bv.x, acc[mt][nt][3] + bv.y);
            *reinterpret_cast<float2*>(out + (size_t)m0 * N_DIM + n0) = v0;
            *reinterpret_cast<float2*>(out + (size_t)(m0 + 8) * N_DIM + n0) = v1;
        }
    }
}

// ---------------------------------------------------------------------------
// Launch: inputs: x, z, lut4, lut5, bias, qweight
// ---------------------------------------------------------------------------
extern "C" void kernel_launch(void* const* d_in, const int* in_sizes, int n_in,
                              void* d_out, int out_size)
{
    const float* x    = (const float*)d_in[0];
    const float* z    = (const float*)d_in[1];
    const float* lut4 = (const float*)d_in[2];
    const float* lut5 = (const float*)d_in[3];
    const float* bias = (const float*)d_in[4];
    const int* qweight = (const int*)d_in[5];
    float* out = (float*)d_out;
    (void)in_sizes; (void)n_in; (void)out_size;

    cudaFuncSetAttribute(gemm_tf32, cudaFuncAttributeMaxDynamicSharedMemorySize, SMEM_BYTES);

    dequant_w<<<(N_DIM * GROUPS) / 256, 256>>>(qweight, lut4, lut5, z);
    convert_x<<<(int)(((size_t)M_DIM * K_DIM / 8) / 256), 256>>>(x);

    dim3 grid(N_DIM / BN, M_DIM / BM);   // (32, 32)
    gemm_tf32<<<grid, 256, SMEM_BYTES>>>(bias, out);
}

// round 8
// speedup vs baseline: 7.2111x; 1.9370x over previous
#include <cuda_runtime.h>
#include <cuda_fp16.h>
#include <cstdint>
#include <math.h>

// ---------------------------------------------------------------------------
// Problem dims
// ---------------------------------------------------------------------------
constexpr int M_DIM = 8192;
constexpr int N_DIM = 4096;
constexpr int K_DIM = 4096;
constexpr int GROUPS = K_DIM / 32;
constexpr int PLANE_STRIDE = N_DIM * GROUPS;

// Scratch (static device arrays = allowed). fp16 operands.
__device__ __half g_xh[(size_t)M_DIM * K_DIM];   // 67 MB
__device__ __half g_wh[(size_t)N_DIM * K_DIM];   // 33 MB

// ---------------------------------------------------------------------------
// Helpers (base ISA only — compute_103-safe)
// ---------------------------------------------------------------------------
__device__ __forceinline__ uint32_t smem_to_u32(const void* p) {
    uint32_t a;
    asm("{ .reg .u64 t; cvta.to.shared.u64 t, %1; cvt.u32.u64 %0, t; }"
        : "=r"(a) : "l"(p));
    return a;
}

#define CP_ASYNC16(dst, src) \
    asm volatile("cp.async.cg.shared.global [%0], [%1], 16;" :: "r"(dst), "l"(src) : "memory")
#define CP_COMMIT() asm volatile("cp.async.commit_group;" ::: "memory")
#define CP_WAIT1()  asm volatile("cp.async.wait_group 1;" ::: "memory")

__device__ __forceinline__ void mma_f16(float* d, const uint32_t* a, const uint32_t* b) {
    asm volatile(
        "mma.sync.aligned.m16n8k16.row.col.f32.f16.f16.f32 "
        "{%0,%1,%2,%3}, {%4,%5,%6,%7}, {%8,%9}, {%0,%1,%2,%3};"
        : "+f"(d[0]), "+f"(d[1]), "+f"(d[2]), "+f"(d[3])
        : "r"(a[0]), "r"(a[1]), "r"(a[2]), "r"(a[3]), "r"(b[0]), "r"(b[1]));
}

// ---------------------------------------------------------------------------
// Kernel 1: dequant + blend -> W fp16
// ---------------------------------------------------------------------------
__global__ __launch_bounds__(256) void dequant_w(
    const int* __restrict__ qw, const float* __restrict__ lut4,
    const float* __restrict__ lut5, const float* __restrict__ zp)
{
    int idx = blockIdx.x * 256 + threadIdx.x;
    int o = idx >> 7;
    int g = idx & (GROUPS - 1);
    int base = o * GROUPS + g;

    unsigned q0 = (unsigned)qw[base];
    unsigned q1 = (unsigned)qw[base + PLANE_STRIDE];
    unsigned q2 = (unsigned)qw[base + 2 * PLANE_STRIDE];
    unsigned q3 = (unsigned)qw[base + 3 * PLANE_STRIDE];
    unsigned q4 = (unsigned)qw[base + 4 * PLANE_STRIDE];

    float z = zp[0];
    float r = 2.0f - 3.0f / (1.0f + expf(-z));   // 2 - 3*sigmoid(z)
    float s = 1.0f - r;

    const float* l4 = lut4 + o * 16;
    const float* l5 = lut5 + o * 32;

    __align__(16) __half vals[32];
#pragma unroll
    for (int b = 0; b < 32; b++) {
        unsigned c4 = (((q0 >> b) & 1u) << 3) | (((q1 >> b) & 1u) << 2)
                    | (((q2 >> b) & 1u) << 1) |  ((q3 >> b) & 1u);
        unsigned c5 = (c4 << 1) | ((q4 >> b) & 1u);
        vals[b] = __float2half_rn(r * l4[c4] + s * l5[c5]);
    }
    __half* dst = g_wh + (size_t)o * K_DIM + g * 32;
    const uint4* sv = reinterpret_cast<const uint4*>(vals);
#pragma unroll
    for (int i = 0; i < 4; i++)
        reinterpret_cast<uint4*>(dst)[i] = sv[i];
}

// ---------------------------------------------------------------------------
// Kernel 2: x -> fp16
// ---------------------------------------------------------------------------
__global__ __launch_bounds__(256) void convert_x(const float* __restrict__ x)
{
    size_t i = ((size_t)blockIdx.x * 256 + threadIdx.x) * 8;
    float4 a = *reinterpret_cast<const float4*>(x + i);
    float4 b = *reinterpret_cast<const float4*>(x + i + 4);
    __align__(16) __half h[8];
    h[0] = __float2half_rn(a.x); h[1] = __float2half_rn(a.y);
    h[2] = __float2half_rn(a.z); h[3] = __float2half_rn(a.w);
    h[4] = __float2half_rn(b.x); h[5] = __float2half_rn(b.y);
    h[6] = __float2half_rn(b.z); h[7] = __float2half_rn(b.w);
    *reinterpret_cast<uint4*>(g_xh + i) = *reinterpret_cast<const uint4*>(h);
}

// ---------------------------------------------------------------------------
// Kernel 3: fp16 mma.sync m16n8k16 GEMM.  out = xh @ wh^T + bias
// CTA 256x128, BK=64, 3-stage cp.async pipeline, 8 warps (4x2), warp 64x64.
// Smem [row][k] fp16 with PITCH=72 halves (144B): conflict-free 32-bit
// fragment loads (bank = (36*grp + qid) mod 32, all distinct).
// ---------------------------------------------------------------------------
constexpr int BM = 256, BN = 128, BK = 64;
constexpr int STAGES = 3;
constexpr int PITCH = 72;                       // halves per smem row
constexpr int ROWS = BM + BN;                   // 384
constexpr int STAGE_HALVES = ROWS * PITCH;      // 27648
constexpr int NCHUNK = K_DIM / BK;              // 64
constexpr int SMEM_BYTES = STAGES * STAGE_HALVES * 2;  // 165888

__global__ __launch_bounds__(256, 1) void gemm_f16(
    const float* __restrict__ bias, float* __restrict__ out)
{
    extern __shared__ __half sm[];
    const int tid = threadIdx.x;
    const int lane = tid & 31, wid = tid >> 5;
    const int wm = wid >> 1, wn = wid & 1;       // warp grid 4x2
    const int grp = lane >> 2, qid = lane & 3;
    const int mBase = blockIdx.y * BM;
    const int nBase = blockIdx.x * BN;

    const __half* Ag = g_xh + (size_t)mBase * K_DIM;
    const __half* Bg = g_wh + (size_t)nBase * K_DIM;
    const uint32_t smAddr = smem_to_u32(sm);

    float acc[4][8][4];
#pragma unroll
    for (int i = 0; i < 4; i++)
#pragma unroll
        for (int j = 0; j < 8; j++)
#pragma unroll
            for (int t = 0; t < 4; t++) acc[i][j][t] = 0.0f;

    // -- async load of one BK-chunk (384 rows x 128B) into stage c%STAGES --
    auto load_chunk = [&](int c) {
        uint32_t stAddr = smAddr + (uint32_t)((c % STAGES) * STAGE_HALVES * 2);
#pragma unroll
        for (int it = 0; it < 12; it++) {        // 3072 16B ops / 256 thr
            int f = tid + it * 256;
            int row = f >> 3;
            int seg = f & 7;                     // 16B (8-half) segment
            const __half* src = (row < BM
                ? Ag + (size_t)row * K_DIM
                : Bg + (size_t)(row - BM) * K_DIM) + c * BK + seg * 8;
            uint32_t dst = stAddr + (uint32_t)((row * PITCH + seg * 8) * 2);
            CP_ASYNC16(dst, src);
        }
    };

    load_chunk(0); CP_COMMIT();
    load_chunk(1); CP_COMMIT();

    for (int c = 0; c < NCHUNK; c++) {
        CP_WAIT1();            // chunk c's group complete
        __syncthreads();

        if (c + 2 < NCHUNK) load_chunk(c + 2);
        CP_COMMIT();           // keep group accounting aligned

        const __half* st = sm + (c % STAGES) * STAGE_HALVES;
#pragma unroll
        for (int ks = 0; ks < 4; ks++) {
            const int k0 = ks * 16;              // k16 step
            uint32_t a[4][4], b[8][2];
#pragma unroll
            for (int mt = 0; mt < 4; mt++) {
                int m = wm * 64 + mt * 16 + grp;
                const __half* p = st + m * PITCH + k0 + 2 * qid;
                a[mt][0] = *reinterpret_cast<const uint32_t*>(p);
                a[mt][1] = *reinterpret_cast<const uint32_t*>(p + 8 * PITCH);
                a[mt][2] = *reinterpret_cast<const uint32_t*>(p + 8);
                a[mt][3] = *reinterpret_cast<const uint32_t*>(p + 8 * PITCH + 8);
            }
#pragma unroll
            for (int nt = 0; nt < 8; nt++) {
                int n = wn * 64 + nt * 8 + grp;
                const __half* p = st + (BM + n) * PITCH + k0 + 2 * qid;
                b[nt][0] = *reinterpret_cast<const uint32_t*>(p);
                b[nt][1] = *reinterpret_cast<const uint32_t*>(p + 8);
            }
#pragma unroll
            for (int mt = 0; mt < 4; mt++)
#pragma unroll
                for (int nt = 0; nt < 8; nt++)
                    mma_f16(acc[mt][nt], a[mt], b[nt]);
        }
    }

    // -- epilogue: bias + float2 stores --
#pragma unroll
    for (int mt = 0; mt < 4; mt++) {
        int m0 = mBase + wm * 64 + mt * 16 + grp;
#pragma unroll
        for (int nt = 0; nt < 8; nt++) {
            int n0 = nBase + wn * 64 + nt * 8 + 2 * qid;
            float2 bv = *reinterpret_cast<const float2*>(bias + n0);
            float2 v0 = make_float2(acc[mt][nt][0] + bv.x, acc[mt][nt][1] + bv.y);
            float2 v1 = make_float2(acc[mt][nt][2] + bv.x, acc[mt][nt][3] + bv.y);
            *reinterpret_cast<float2*>(out + (size_t)m0 * N_DIM + n0) = v0;
            *reinterpret_cast<float2*>(out + (size_t)(m0 + 8) * N_DIM + n0) = v1;
        }
    }
}

// ---------------------------------------------------------------------------
// Launch: inputs: x, z, lut4, lut5, bias, qweight
// ---------------------------------------------------------------------------
extern "C" void kernel_launch(void* const* d_in, const int* in_sizes, int n_in,
                              void* d_out, int out_size)
{
    const float* x    = (const float*)d_in[0];
    const float* z    = (const float*)d_in[1];
    const float* lut4 = (const float*)d_in[2];
    const float* lut5 = (const float*)d_in[3];
    const float* bias = (const float*)d_in[4];
    const int* qweight = (const int*)d_in[5];
    float* out = (float*)d_out;
    (void)in_sizes; (void)n_in; (void)out_size;

    cudaFuncSetAttribute(gemm_f16, cudaFuncAttributeMaxDynamicSharedMemorySize, SMEM_BYTES);

    dequant_w<<<(N_DIM * GROUPS) / 256, 256>>>(qweight, lut4, lut5, z);
    convert_x<<<(int)(((size_t)M_DIM * K_DIM / 8) / 256), 256>>>(x);

    dim3 grid(N_DIM / BN, M_DIM / BM);   // (32, 32)
    gemm_f16<<<grid, 256, SMEM_BYTES>>>(bias, out);
}